// round 1
// baseline (speedup 1.0000x reference)
#include <cuda_runtime.h>
#include <math.h>

#define EMB    4096
#define DIM    4096
#define TPREV  8192
#define TTOT   (TPREV + 1)     // 8193
#define NCHUNK 8
#define CHUNK  (EMB / NCHUNK)  // 512
#define TPAD   8224            // padded stride for partials

// Scratch (device globals — no allocation allowed)
__device__ __align__(16) float g_q[DIM];
__device__ __align__(16) float g_k[DIM];
__device__ __align__(16) float g_v[DIM];
__device__ __align__(16) float g_part[NCHUNK * TPAD];
__device__ __align__(16) float g_a[TTOT + 3];

// ---------------------------------------------------------------------------
// Kernel 1: q/k/v = W{q,k,v} @ x  — warp per output row, float4 streaming.
// 3*4096 rows = 12288 warps.
// ---------------------------------------------------------------------------
__global__ void qkv_kernel(const float* __restrict__ x,
                           const float* __restrict__ Wq,
                           const float* __restrict__ Wk,
                           const float* __restrict__ Wv) {
    int gw   = (blockIdx.x * blockDim.x + threadIdx.x) >> 5;
    int lane = threadIdx.x & 31;
    if (gw >= 3 * DIM) return;
    int which = gw >> 12;          // gw / 4096
    int row   = gw & (DIM - 1);

    const float* W = (which == 0) ? Wq : (which == 1) ? Wk : Wv;
    const float4* wr = reinterpret_cast<const float4*>(W) + (size_t)row * (EMB / 4);
    const float4* xv = reinterpret_cast<const float4*>(x);

    float acc = 0.0f;
#pragma unroll 8
    for (int i = lane; i < EMB / 4; i += 32) {
        float4 w  = wr[i];
        float4 xx = xv[i];
        acc += w.x * xx.x + w.y * xx.y + w.z * xx.z + w.w * xx.w;
    }
#pragma unroll
    for (int off = 16; off; off >>= 1)
        acc += __shfl_xor_sync(0xffffffffu, acc, off);

    if (lane == 0) {
        float* dst = (which == 0) ? g_q : (which == 1) ? g_k : g_v;
        dst[row] = acc;
    }
}

// ---------------------------------------------------------------------------
// Kernel 2: partial scores. Grid (ceil(8193/256), NCHUNK).
// Each block: 256 consecutive t, one 512-wide d-chunk. Coalesced over t.
// Deterministic partials (no float atomics).
// ---------------------------------------------------------------------------
__global__ void score_partial_kernel(const float* __restrict__ Kc) {
    __shared__ float sq[CHUNK];
    int c  = blockIdx.y;
    int d0 = c * CHUNK;
    for (int i = threadIdx.x; i < CHUNK; i += blockDim.x)
        sq[i] = g_q[d0 + i];
    __syncthreads();

    int t = blockIdx.x * blockDim.x + threadIdx.x;
    if (t >= TTOT) return;

    float acc = 0.0f;
    if (t < TPREV) {
        const float* col = Kc + (size_t)d0 * TPREV + t;
#pragma unroll 8
        for (int d = 0; d < CHUNK; d++)
            acc += sq[d] * col[(size_t)d * TPREV];
    } else {
        // current-step key column
#pragma unroll 8
        for (int d = 0; d < CHUNK; d++)
            acc += sq[d] * g_k[d0 + d];
    }
    g_part[c * TPAD + t] = acc;
}

// ---------------------------------------------------------------------------
// Kernel 3: reduce partials -> sigmoid scores.
// ---------------------------------------------------------------------------
__global__ void sigmoid_kernel() {
    int t = blockIdx.x * blockDim.x + threadIdx.x;
    if (t >= TTOT) return;
    float s = 0.0f;
#pragma unroll
    for (int c = 0; c < NCHUNK; c++)
        s += g_part[c * TPAD + t];
    s *= 0.015625f;  // 1/sqrt(4096)
    g_a[t] = 1.0f / (1.0f + expf(-s));
}

// ---------------------------------------------------------------------------
// Kernel 4: z[d] = V_cache[d,:] . a[0:T] + v[d]*a[T].
// 8 rows per block (warp per row); a[] staged in 32KB smem.
// ---------------------------------------------------------------------------
__global__ void out_kernel(const float* __restrict__ Vc, float* __restrict__ out) {
    __shared__ float4 sa[TPREV / 4];
    const float4* av = reinterpret_cast<const float4*>(g_a);
    for (int i = threadIdx.x; i < TPREV / 4; i += blockDim.x)
        sa[i] = av[i];
    __syncthreads();

    int warp = threadIdx.x >> 5;
    int lane = threadIdx.x & 31;
    int row  = blockIdx.x * 8 + warp;
    if (row >= DIM) return;

    const float4* vr = reinterpret_cast<const float4*>(Vc) + (size_t)row * (TPREV / 4);
    float acc = 0.0f;
#pragma unroll 8
    for (int i = lane; i < TPREV / 4; i += 32) {
        float4 v = vr[i];
        float4 a = sa[i];
        acc += v.x * a.x + v.y * a.y + v.z * a.z + v.w * a.w;
    }
#pragma unroll
    for (int off = 16; off; off >>= 1)
        acc += __shfl_xor_sync(0xffffffffu, acc, off);

    if (lane == 0)
        out[row] = acc + g_v[row] * g_a[TPREV];
}

// ---------------------------------------------------------------------------
extern "C" void kernel_launch(void* const* d_in, const int* in_sizes, int n_in,
                              void* d_out, int out_size) {
    const float* x  = (const float*)d_in[0];
    const float* Wq = (const float*)d_in[1];
    const float* Wk = (const float*)d_in[2];
    const float* Wv = (const float*)d_in[3];
    const float* Kc = (const float*)d_in[4];
    const float* Vc = (const float*)d_in[5];
    float* out = (float*)d_out;

    // 1) q,k,v GEMVs: 12288 warps
    qkv_kernel<<<(3 * DIM * 32) / 256, 256>>>(x, Wq, Wk, Wv);

    // 2) score partials: (33, 8) blocks
    dim3 sg((TTOT + 255) / 256, NCHUNK);
    score_partial_kernel<<<sg, 256>>>(Kc);

    // 3) reduce + sigmoid
    sigmoid_kernel<<<(TTOT + 255) / 256, 256>>>();

    // 4) output GEMV
    out_kernel<<<DIM / 8, 256>>>(Vc, out);
}

// round 2
// speedup vs baseline: 1.1470x; 1.1470x over previous
#include <cuda_runtime.h>
#include <math.h>

#define EMB    4096
#define DIM    4096
#define TPREV  8192
#define TTOT   (TPREV + 1)     // 8193
#define NCHUNK 32
#define CHUNK  (EMB / NCHUNK)  // 128
#define TPAD   8224            // padded stride for partials (mult of 32)

// Scratch (device globals — no allocation allowed)
__device__ __align__(16) float g_q[DIM];
__device__ __align__(16) float g_k[DIM];
__device__ __align__(16) float g_v[DIM];
__device__ __align__(16) float g_part[NCHUNK * TPAD];
__device__ __align__(16) float g_a[TTOT + 3];

// ---------------------------------------------------------------------------
// Kernel 1: q/k/v = W{q,k,v} @ x  — warp per output row, float4 streaming,
// fully unrolled so ptxas front-batches loads (high MLP).
// ---------------------------------------------------------------------------
__global__ void qkv_kernel(const float* __restrict__ x,
                           const float* __restrict__ Wq,
                           const float* __restrict__ Wk,
                           const float* __restrict__ Wv) {
    int gw   = (blockIdx.x * blockDim.x + threadIdx.x) >> 5;
    int lane = threadIdx.x & 31;
    if (gw >= 3 * DIM) return;
    int which = gw >> 12;
    int row   = gw & (DIM - 1);

    const float* W = (which == 0) ? Wq : (which == 1) ? Wk : Wv;
    const float4* wr = reinterpret_cast<const float4*>(W) + (size_t)row * (EMB / 4);
    const float4* xv = reinterpret_cast<const float4*>(x);

    float acc0 = 0.0f, acc1 = 0.0f;
#pragma unroll
    for (int j = 0; j < 16; j++) {           // 32 float4 per lane, 2 accumulators
        int i0 = lane + (2 * j) * 32;
        int i1 = lane + (2 * j + 1) * 32;
        float4 w0 = wr[i0], x0 = __ldg(&xv[i0]);
        float4 w1 = wr[i1], x1 = __ldg(&xv[i1]);
        acc0 += w0.x * x0.x + w0.y * x0.y + w0.z * x0.z + w0.w * x0.w;
        acc1 += w1.x * x1.x + w1.y * x1.y + w1.z * x1.z + w1.w * x1.w;
    }
    float acc = acc0 + acc1;
#pragma unroll
    for (int off = 16; off; off >>= 1)
        acc += __shfl_xor_sync(0xffffffffu, acc, off);

    if (lane == 0) {
        float* dst = (which == 0) ? g_q : (which == 1) ? g_k : g_v;
        dst[row] = acc;
    }
}

// ---------------------------------------------------------------------------
// Kernel 2: partial scores. Grid (16, 32), block 128.
// Each thread owns 4 consecutive t (float4 along t). Chunk of 128 d per block.
// Deterministic partials (no float atomics). t=8192 tail handled in kernel 3.
// ---------------------------------------------------------------------------
__global__ void score_partial_kernel(const float* __restrict__ Kc) {
    __shared__ float sq[CHUNK];
    int c  = blockIdx.y;
    int d0 = c * CHUNK;
    if (threadIdx.x < CHUNK)
        sq[threadIdx.x] = g_q[d0 + threadIdx.x];
    __syncthreads();

    int t4 = blockIdx.x * (blockDim.x) + threadIdx.x;       // float4 index along t
    const float4* col = reinterpret_cast<const float4*>(Kc) +
                        (size_t)d0 * (TPREV / 4) + t4;

    float4 acc = make_float4(0.f, 0.f, 0.f, 0.f);
#pragma unroll 8
    for (int d = 0; d < CHUNK; d++) {
        float4 kk = col[(size_t)d * (TPREV / 4)];
        float  s  = sq[d];
        acc.x += s * kk.x; acc.y += s * kk.y;
        acc.z += s * kk.z; acc.w += s * kk.w;
    }
    reinterpret_cast<float4*>(g_part + c * TPAD)[t4] = acc;
}

// ---------------------------------------------------------------------------
// Kernel 3: reduce partials -> sigmoid scores. Grid 33 blocks of 256:
// blocks 0..31 reduce 8192 t; block 32 computes the t=8192 tail (q·k dot).
// ---------------------------------------------------------------------------
__global__ void sigmoid_kernel() {
    if (blockIdx.x < 32) {
        int t = blockIdx.x * 256 + threadIdx.x;
        float s = 0.0f;
#pragma unroll
        for (int c = 0; c < NCHUNK; c++)
            s += g_part[c * TPAD + t];
        s *= 0.015625f;  // 1/sqrt(4096)
        g_a[t] = 1.0f / (1.0f + expf(-s));
    } else {
        // tail: a[8192] = sigmoid(q.k / 64)
        __shared__ float red[256];
        float s = 0.0f;
#pragma unroll
        for (int j = 0; j < 16; j++) {
            int d = threadIdx.x + 256 * j;
            s += g_q[d] * g_k[d];
        }
        red[threadIdx.x] = s;
        __syncthreads();
#pragma unroll
        for (int w = 128; w >= 1; w >>= 1) {
            if (threadIdx.x < w) red[threadIdx.x] += red[threadIdx.x + w];
            __syncthreads();
        }
        if (threadIdx.x == 0) {
            float v = red[0] * 0.015625f;
            g_a[TPREV] = 1.0f / (1.0f + expf(-v));
        }
    }
}

// ---------------------------------------------------------------------------
// Kernel 4: z[d] = V_cache[d,:] . a[0:T] + v[d]*a[T].
// Warp per row, no smem (a lives in L1), 512 blocks of 256.
// ---------------------------------------------------------------------------
__global__ void out_kernel(const float* __restrict__ Vc, float* __restrict__ out) {
    int warp = threadIdx.x >> 5;
    int lane = threadIdx.x & 31;
    int row  = blockIdx.x * 8 + warp;

    const float4* vr = reinterpret_cast<const float4*>(Vc) + (size_t)row * (TPREV / 4);
    const float4* av = reinterpret_cast<const float4*>(g_a);

    float acc0 = 0.0f, acc1 = 0.0f;
#pragma unroll 8
    for (int j = 0; j < 32; j++) {           // 64 float4 per lane
        int i0 = lane + (2 * j) * 32;
        int i1 = lane + (2 * j + 1) * 32;
        float4 v0 = vr[i0], a0 = __ldg(&av[i0]);
        float4 v1 = vr[i1], a1 = __ldg(&av[i1]);
        acc0 += v0.x * a0.x + v0.y * a0.y + v0.z * a0.z + v0.w * a0.w;
        acc1 += v1.x * a1.x + v1.y * a1.y + v1.z * a1.z + v1.w * a1.w;
    }
    float acc = acc0 + acc1;
#pragma unroll
    for (int off = 16; off; off >>= 1)
        acc += __shfl_xor_sync(0xffffffffu, acc, off);

    if (lane == 0)
        out[row] = acc + g_v[row] * g_a[TPREV];
}

// ---------------------------------------------------------------------------
extern "C" void kernel_launch(void* const* d_in, const int* in_sizes, int n_in,
                              void* d_out, int out_size) {
    const float* x  = (const float*)d_in[0];
    const float* Wq = (const float*)d_in[1];
    const float* Wk = (const float*)d_in[2];
    const float* Wv = (const float*)d_in[3];
    const float* Kc = (const float*)d_in[4];
    const float* Vc = (const float*)d_in[5];
    float* out = (float*)d_out;

    qkv_kernel<<<(3 * DIM) / 8, 256>>>(x, Wq, Wk, Wv);

    dim3 sg(TPREV / (128 * 4), NCHUNK);          // (16, 32)
    score_partial_kernel<<<sg, 128>>>(Kc);

    sigmoid_kernel<<<33, 256>>>();

    out_kernel<<<DIM / 8, 256>>>(Vc, out);
}

// round 3
// speedup vs baseline: 1.1639x; 1.0147x over previous
#include <cuda_runtime.h>
#include <math.h>

#define EMB    4096
#define DIM    4096
#define TPREV  8192
#define TTOT   (TPREV + 1)     // 8193
#define NCHUNK 64
#define CHUNK  (EMB / NCHUNK)  // 64
#define TPAD   8224            // padded stride for partials (mult of 32)

// Scratch (device globals — no allocation allowed)
__device__ __align__(16) float g_q[DIM];
__device__ __align__(16) float g_k[DIM];
__device__ __align__(16) float g_v[DIM];
__device__ __align__(16) float g_part[NCHUNK * TPAD];
__device__ __align__(16) float g_a[TTOT + 3];

__device__ __forceinline__ float warp_red(float v) {
#pragma unroll
    for (int off = 16; off; off >>= 1)
        v += __shfl_xor_sync(0xffffffffu, v, off);
    return v;
}

// ---------------------------------------------------------------------------
// Kernel 1: q/k/v = W{q,k,v} @ x — TWO warps per output row (half the E range
// each), smem combine. 3*4096 rows -> 24576 warps -> 3072 blocks of 256.
// ---------------------------------------------------------------------------
__global__ void qkv_kernel(const float* __restrict__ x,
                           const float* __restrict__ Wq,
                           const float* __restrict__ Wk,
                           const float* __restrict__ Wv) {
    __shared__ float part[8];
    int warp = threadIdx.x >> 5;
    int lane = threadIdx.x & 31;
    int rowInBlk = warp >> 1;                 // 0..3
    int half     = warp & 1;
    int gr  = blockIdx.x * 4 + rowInBlk;      // 0..12287
    int which = gr >> 12;
    int row   = gr & (DIM - 1);

    const float* W = (which == 0) ? Wq : (which == 1) ? Wk : Wv;
    const float4* wr = reinterpret_cast<const float4*>(W) + (size_t)row * (EMB / 4)
                       + half * (EMB / 8);
    const float4* xv = reinterpret_cast<const float4*>(x) + half * (EMB / 8);

    float acc0 = 0.0f, acc1 = 0.0f;
#pragma unroll
    for (int j = 0; j < 8; j++) {             // 16 float4 per lane
        int i0 = lane + (2 * j) * 32;
        int i1 = lane + (2 * j + 1) * 32;
        float4 w0 = wr[i0], x0 = __ldg(&xv[i0]);
        float4 w1 = wr[i1], x1 = __ldg(&xv[i1]);
        acc0 += w0.x * x0.x + w0.y * x0.y + w0.z * x0.z + w0.w * x0.w;
        acc1 += w1.x * x1.x + w1.y * x1.y + w1.z * x1.z + w1.w * x1.w;
    }
    float acc = warp_red(acc0 + acc1);
    if (lane == 0) part[warp] = acc;
    __syncthreads();

    if (threadIdx.x < 4) {
        int gr2 = blockIdx.x * 4 + threadIdx.x;
        int wh2 = gr2 >> 12, rw2 = gr2 & (DIM - 1);
        float* dst = (wh2 == 0) ? g_q : (wh2 == 1) ? g_k : g_v;
        dst[rw2] = part[2 * threadIdx.x] + part[2 * threadIdx.x + 1];
    }
}

// ---------------------------------------------------------------------------
// Kernel 2: partial scores. Grid (8, 64), block 256 -> 4096 warps.
// Thread owns one float4 along t, chunk of 64 d. Deterministic partials.
// t=8192 tail handled in kernel 3.
// ---------------------------------------------------------------------------
__global__ void score_partial_kernel(const float* __restrict__ Kc) {
    __shared__ float sq[CHUNK];
    int c  = blockIdx.y;
    int d0 = c * CHUNK;
    if (threadIdx.x < CHUNK)
        sq[threadIdx.x] = g_q[d0 + threadIdx.x];
    __syncthreads();

    int t4 = blockIdx.x * blockDim.x + threadIdx.x;   // 0..2047
    const float4* col = reinterpret_cast<const float4*>(Kc) +
                        (size_t)d0 * (TPREV / 4) + t4;

    float4 acc = make_float4(0.f, 0.f, 0.f, 0.f);
#pragma unroll 8
    for (int d = 0; d < CHUNK; d++) {
        float4 kk = col[(size_t)d * (TPREV / 4)];
        float  s  = sq[d];
        acc.x += s * kk.x; acc.y += s * kk.y;
        acc.z += s * kk.z; acc.w += s * kk.w;
    }
    reinterpret_cast<float4*>(g_part + c * TPAD)[t4] = acc;
}

// ---------------------------------------------------------------------------
// Kernel 3: reduce partials -> sigmoid scores. 33 blocks of 256:
// blocks 0..31 reduce over 64 chunks; block 32 computes the t=8192 tail.
// ---------------------------------------------------------------------------
__global__ void sigmoid_kernel() {
    if (blockIdx.x < 32) {
        int t = blockIdx.x * 256 + threadIdx.x;
        float s = 0.0f;
#pragma unroll
        for (int c = 0; c < NCHUNK; c++)
            s += g_part[c * TPAD + t];
        s *= 0.015625f;  // 1/sqrt(4096)
        g_a[t] = 1.0f / (1.0f + expf(-s));
    } else {
        __shared__ float red[256];
        float s = 0.0f;
#pragma unroll
        for (int j = 0; j < 16; j++) {
            int d = threadIdx.x + 256 * j;
            s += g_q[d] * g_k[d];
        }
        red[threadIdx.x] = s;
        __syncthreads();
#pragma unroll
        for (int w = 128; w >= 1; w >>= 1) {
            if (threadIdx.x < w) red[threadIdx.x] += red[threadIdx.x + w];
            __syncthreads();
        }
        if (threadIdx.x == 0) {
            float v = red[0] * 0.015625f;
            g_a[TPREV] = 1.0f / (1.0f + expf(-v));
        }
    }
}

// ---------------------------------------------------------------------------
// Kernel 4: z[d] = V_cache[d,:] . a[0:T] + v[d]*a[T].
// TWO warps per row (half the t-range each), smem combine.
// 4096 rows -> 8192 warps -> 1024 blocks of 256.
// ---------------------------------------------------------------------------
__global__ void out_kernel(const float* __restrict__ Vc, float* __restrict__ out) {
    __shared__ float part[8];
    int warp = threadIdx.x >> 5;
    int lane = threadIdx.x & 31;
    int rowInBlk = warp >> 1;
    int half     = warp & 1;
    int row = blockIdx.x * 4 + rowInBlk;

    const float4* vr = reinterpret_cast<const float4*>(Vc) + (size_t)row * (TPREV / 4)
                       + half * (TPREV / 8);
    const float4* av = reinterpret_cast<const float4*>(g_a) + half * (TPREV / 8);

    float acc0 = 0.0f, acc1 = 0.0f;
#pragma unroll 8
    for (int j = 0; j < 16; j++) {            // 32 float4 per lane
        int i0 = lane + (2 * j) * 32;
        int i1 = lane + (2 * j + 1) * 32;
        float4 v0 = vr[i0], a0 = __ldg(&av[i0]);
        float4 v1 = vr[i1], a1 = __ldg(&av[i1]);
        acc0 += v0.x * a0.x + v0.y * a0.y + v0.z * a0.z + v0.w * a0.w;
        acc1 += v1.x * a1.x + v1.y * a1.y + v1.z * a1.z + v1.w * a1.w;
    }
    float acc = warp_red(acc0 + acc1);
    if (lane == 0) part[warp] = acc;
    __syncthreads();

    if (threadIdx.x < 4) {
        int r2 = blockIdx.x * 4 + threadIdx.x;
        out[r2] = part[2 * threadIdx.x] + part[2 * threadIdx.x + 1]
                  + g_v[r2] * g_a[TPREV];
    }
}

// ---------------------------------------------------------------------------
extern "C" void kernel_launch(void* const* d_in, const int* in_sizes, int n_in,
                              void* d_out, int out_size) {
    const float* x  = (const float*)d_in[0];
    const float* Wq = (const float*)d_in[1];
    const float* Wk = (const float*)d_in[2];
    const float* Wv = (const float*)d_in[3];
    const float* Kc = (const float*)d_in[4];
    const float* Vc = (const float*)d_in[5];
    float* out = (float*)d_out;

    qkv_kernel<<<(3 * DIM) / 4, 256>>>(x, Wq, Wk, Wv);

    dim3 sg(TPREV / (256 * 4), NCHUNK);          // (8, 64)
    score_partial_kernel<<<sg, 256>>>(Kc);

    sigmoid_kernel<<<33, 256>>>();

    out_kernel<<<DIM / 4, 256>>>(Vc, out);
}

// round 4
// speedup vs baseline: 1.2938x; 1.1117x over previous
#include <cuda_runtime.h>
#include <math.h>

#define EMB    4096
#define DIM    4096
#define TPREV  8192
#define TTOT   (TPREV + 1)     // 8193
#define NCHUNK 64
#define CHUNK  (EMB / NCHUNK)  // 64
#define TPAD   8224            // padded stride for partials (mult of 32)

// Scratch (device globals — no allocation allowed)
__device__ __align__(16) float g_q[DIM];
__device__ __align__(16) float g_k[DIM];
__device__ __align__(16) float g_v[DIM];
__device__ __align__(16) float g_part[NCHUNK * TPAD];
__device__ __align__(16) float g_a[TTOT + 3];

__device__ __forceinline__ float warp_red(float v) {
#pragma unroll
    for (int off = 16; off; off >>= 1)
        v += __shfl_xor_sync(0xffffffffu, v, off);
    return v;
}

// ---------------------------------------------------------------------------
// Kernel 1: q/k/v = W{q,k,v} @ x — ONE warp per output row, deep load batches:
// 4 batches x (8 W-loads + 8 x-loads) of independent LDG.128 per lane.
// 12288 warps -> 1536 blocks of 256.
// ---------------------------------------------------------------------------
__global__ void __launch_bounds__(256, 4)
qkv_kernel(const float* __restrict__ x,
           const float* __restrict__ Wq,
           const float* __restrict__ Wk,
           const float* __restrict__ Wv) {
    int gw   = (blockIdx.x * blockDim.x + threadIdx.x) >> 5;
    int lane = threadIdx.x & 31;
    int which = gw >> 12;
    int row   = gw & (DIM - 1);

    const float* W = (which == 0) ? Wq : (which == 1) ? Wk : Wv;
    const float4* wr = reinterpret_cast<const float4*>(W) + (size_t)row * (EMB / 4);
    const float4* xv = reinterpret_cast<const float4*>(x);

    float acc = 0.0f;
#pragma unroll
    for (int b = 0; b < 4; b++) {            // 4 batches of 8 float4 per lane
        float4 w[8], xx[8];
#pragma unroll
        for (int j = 0; j < 8; j++) {
            int i = lane + (b * 8 + j) * 32;
            w[j]  = wr[i];
            xx[j] = __ldg(&xv[i]);
        }
#pragma unroll
        for (int j = 0; j < 8; j++)
            acc += w[j].x * xx[j].x + w[j].y * xx[j].y
                 + w[j].z * xx[j].z + w[j].w * xx[j].w;
    }
    acc = warp_red(acc);

    if (lane == 0) {
        float* dst = (which == 0) ? g_q : (which == 1) ? g_k : g_v;
        dst[row] = acc;
    }
}

// ---------------------------------------------------------------------------
// Kernel 2: partial scores. Grid (8, 64), block 256 -> 4096 warps.
// Thread owns one float4 along t, chunk of 64 d; all K loads independent,
// unroll 16 so ptxas front-batches 16 LDG.128. Deterministic partials.
// t=8192 tail handled in kernel 3.
// ---------------------------------------------------------------------------
__global__ void __launch_bounds__(256, 4)
score_partial_kernel(const float* __restrict__ Kc) {
    __shared__ float sq[CHUNK];
    int c  = blockIdx.y;
    int d0 = c * CHUNK;
    if (threadIdx.x < CHUNK)
        sq[threadIdx.x] = g_q[d0 + threadIdx.x];
    __syncthreads();

    int t4 = blockIdx.x * blockDim.x + threadIdx.x;   // 0..2047
    const float4* col = reinterpret_cast<const float4*>(Kc) +
                        (size_t)d0 * (TPREV / 4) + t4;

    float4 acc = make_float4(0.f, 0.f, 0.f, 0.f);
#pragma unroll 16
    for (int d = 0; d < CHUNK; d++) {
        float4 kk = col[(size_t)d * (TPREV / 4)];
        float  s  = sq[d];
        acc.x += s * kk.x; acc.y += s * kk.y;
        acc.z += s * kk.z; acc.w += s * kk.w;
    }
    reinterpret_cast<float4*>(g_part + c * TPAD)[t4] = acc;
}

// ---------------------------------------------------------------------------
// Kernel 3: reduce partials -> sigmoid scores. 33 blocks of 256:
// blocks 0..31 reduce over 64 chunks; block 32 computes the t=8192 tail.
// ---------------------------------------------------------------------------
__global__ void sigmoid_kernel() {
    if (blockIdx.x < 32) {
        int t = blockIdx.x * 256 + threadIdx.x;
        float s = 0.0f;
#pragma unroll
        for (int c = 0; c < NCHUNK; c++)
            s += g_part[c * TPAD + t];
        s *= 0.015625f;  // 1/sqrt(4096)
        g_a[t] = 1.0f / (1.0f + expf(-s));
    } else {
        __shared__ float red[256];
        float s = 0.0f;
#pragma unroll
        for (int j = 0; j < 16; j++) {
            int d = threadIdx.x + 256 * j;
            s += g_q[d] * g_k[d];
        }
        red[threadIdx.x] = s;
        __syncthreads();
#pragma unroll
        for (int w = 128; w >= 1; w >>= 1) {
            if (threadIdx.x < w) red[threadIdx.x] += red[threadIdx.x + w];
            __syncthreads();
        }
        if (threadIdx.x == 0) {
            float v = red[0] * 0.015625f;
            g_a[TPREV] = 1.0f / (1.0f + expf(-v));
        }
    }
}

// ---------------------------------------------------------------------------
// Kernel 4: z[d] = V_cache[d,:] . a[0:T] + v[d]*a[T].
// ONE warp per row; 8 batches x (8 V-loads + 8 a-loads) independent LDG.128.
// 4096 warps -> 512 blocks of 256.
// ---------------------------------------------------------------------------
__global__ void __launch_bounds__(256, 4)
out_kernel(const float* __restrict__ Vc, float* __restrict__ out) {
    int warp = threadIdx.x >> 5;
    int lane = threadIdx.x & 31;
    int row  = blockIdx.x * 8 + warp;

    const float4* vr = reinterpret_cast<const float4*>(Vc) + (size_t)row * (TPREV / 4);
    const float4* av = reinterpret_cast<const float4*>(g_a);

    float acc = 0.0f;
#pragma unroll
    for (int b = 0; b < 8; b++) {            // 8 batches of 8 float4 per lane
        float4 v[8], a[8];
#pragma unroll
        for (int j = 0; j < 8; j++) {
            int i = lane + (b * 8 + j) * 32;
            v[j] = vr[i];
            a[j] = __ldg(&av[i]);
        }
#pragma unroll
        for (int j = 0; j < 8; j++)
            acc += v[j].x * a[j].x + v[j].y * a[j].y
                 + v[j].z * a[j].z + v[j].w * a[j].w;
    }
    acc = warp_red(acc);

    if (lane == 0)
        out[row] = acc + g_v[row] * g_a[TPREV];
}

// ---------------------------------------------------------------------------
extern "C" void kernel_launch(void* const* d_in, const int* in_sizes, int n_in,
                              void* d_out, int out_size) {
    const float* x  = (const float*)d_in[0];
    const float* Wq = (const float*)d_in[1];
    const float* Wk = (const float*)d_in[2];
    const float* Wv = (const float*)d_in[3];
    const float* Kc = (const float*)d_in[4];
    const float* Vc = (const float*)d_in[5];
    float* out = (float*)d_out;

    qkv_kernel<<<(3 * DIM) / 8, 256>>>(x, Wq, Wk, Wv);

    dim3 sg(TPREV / (256 * 4), NCHUNK);          // (8, 64)
    score_partial_kernel<<<sg, 256>>>(Kc);

    sigmoid_kernel<<<33, 256>>>();

    out_kernel<<<DIM / 8, 256>>>(Vc, out);
}